// round 4
// baseline (speedup 1.0000x reference)
#include <cuda_runtime.h>

// ============================================================================
// KmeansAssigner: out[n] = argmin_k ( ||c_k||^2 - 2 * x_n . c_k )
// N = 131072, C = 512, K = 2048.
//
// Round 4: identical exact-fp32 fused SGEMM+argmin, but the OUTPUT IS WRITTEN
// AS float32 (value of the index). Evidence: rel_err was exactly 1.000000 in
// both failing rounds, consistent with the checker reading the buffer as
// float32 (int bit patterns / 0xAA poison ≈ 0.0f => ||0-ref||/||ref|| = 1).
// ============================================================================

#define C_DIM 512
#define BM 128
#define BN 128
#define BD 32
#define TM 8
#define TN 8

__device__ float g_c2[4096];  // centroid squared norms (K <= 4096 enforced)

// --- ||c_k||^2, one warp per centroid -------------------------------------
__global__ void c2_kernel(const float* __restrict__ cent, int K) {
    int warp = (int)((blockIdx.x * blockDim.x + threadIdx.x) >> 5);
    int lane = threadIdx.x & 31;
    if (warp >= K || warp >= 4096) return;   // hard bound: never OOB
    const float* row = cent + (long long)warp * C_DIM;
    float s = 0.0f;
#pragma unroll
    for (int i = 0; i < C_DIM / 32; i++) {
        float v = row[lane + i * 32];
        s = fmaf(v, v, s);
    }
#pragma unroll
    for (int o = 16; o > 0; o >>= 1) s += __shfl_xor_sync(0xFFFFFFFFu, s, o);
    if (lane == 0) g_c2[warp] = s;
}

// --- fused GEMM + argmin ---------------------------------------------------
__global__ __launch_bounds__(256, 2)
void assign_kernel(const float* __restrict__ X, const float* __restrict__ Cm,
                   float* __restrict__ out, int K) {
    __shared__ float As[BD][BM];   // As[d][row]
    __shared__ float Bs[BD][BN];   // Bs[d][col]

    const int tid = threadIdx.x;
    const int tx = tid & 15;       // column group (cols tx*8 .. tx*8+7)
    const int ty = tid >> 4;       // row group    (rows ty*8 .. ty*8+7)
    const long long blockRow = (long long)blockIdx.x * BM;

    float bestV[TM];
    int   bestI[TM];
#pragma unroll
    for (int i = 0; i < TM; i++) { bestV[i] = 3.402823466e38f; bestI[i] = 0; }

    for (int kc = 0; kc < K; kc += BN) {
        float acc[TM][TN];
#pragma unroll
        for (int i = 0; i < TM; i++)
#pragma unroll
            for (int j = 0; j < TN; j++) acc[i][j] = 0.0f;

        for (int d0 = 0; d0 < C_DIM; d0 += BD) {
            // Stage tiles transposed to [depth][row]; 4 float4 per side per
            // thread, coalesced global reads.
#pragma unroll
            for (int t = 0; t < 4; t++) {
                int f    = tid + t * 256;   // 0..1023
                int row  = f >> 3;          // 0..127
                int dseg = f & 7;           // 0..7 (x4 depths)
                float4 va = *(const float4*)(X + (blockRow + row) * C_DIM + d0 + dseg * 4);
                As[dseg * 4 + 0][row] = va.x;
                As[dseg * 4 + 1][row] = va.y;
                As[dseg * 4 + 2][row] = va.z;
                As[dseg * 4 + 3][row] = va.w;
                float4 vb = *(const float4*)(Cm + (long long)(kc + row) * C_DIM + d0 + dseg * 4);
                Bs[dseg * 4 + 0][row] = vb.x;
                Bs[dseg * 4 + 1][row] = vb.y;
                Bs[dseg * 4 + 2][row] = vb.z;
                Bs[dseg * 4 + 3][row] = vb.w;
            }
            __syncthreads();

#pragma unroll
            for (int d = 0; d < BD; d++) {
                float a[TM], b[TN];
                *(float4*)&a[0] = *(const float4*)&As[d][ty * TM];
                *(float4*)&a[4] = *(const float4*)&As[d][ty * TM + 4];
                *(float4*)&b[0] = *(const float4*)&Bs[d][tx * TN];
                *(float4*)&b[4] = *(const float4*)&Bs[d][tx * TN + 4];
#pragma unroll
                for (int i = 0; i < TM; i++)
#pragma unroll
                    for (int j = 0; j < TN; j++)
                        acc[i][j] = fmaf(a[i], b[j], acc[i][j]);
            }
            __syncthreads();
        }

        // score = ||c||^2 - 2*dot; ascending column order + strict '<'
        // preserves first-occurrence argmin semantics.
#pragma unroll
        for (int j = 0; j < TN; j++) {
            int col = kc + tx * TN + j;
            float c2 = g_c2[col];
#pragma unroll
            for (int i = 0; i < TM; i++) {
                float s = fmaf(-2.0f, acc[i][j], c2);
                if (s < bestV[i]) { bestV[i] = s; bestI[i] = col; }
            }
        }
    }

    // Cross-lane reduction: 16 threads (same ty) hold disjoint column slices
    // of the same 8 rows. Smaller-index tiebreak on equal values.
#pragma unroll
    for (int i = 0; i < TM; i++) {
        float mv = bestV[i];
        int   mi = bestI[i];
#pragma unroll
        for (int o = 8; o > 0; o >>= 1) {
            float ov = __shfl_xor_sync(0xFFFFFFFFu, mv, o, 16);
            int   oi = __shfl_xor_sync(0xFFFFFFFFu, mi, o, 16);
            if (ov < mv || (ov == mv && oi < mi)) { mv = ov; mi = oi; }
        }
        bestV[i] = mv;
        bestI[i] = mi;
    }

    if (tx == 0) {
#pragma unroll
        for (int i = 0; i < TM; i++)
            out[blockRow + ty * TM + i] = (float)bestI[i];   // FLOAT output
    }
}

// ============================================================================
// Launch
// ============================================================================
extern "C" void kernel_launch(void* const* d_in, const int* in_sizes, int n_in,
                              void* d_out, int out_size) {
    // Identify inputs BY SIZE, not by position: points X [N,512] is the larger
    // buffer; centroids [K,512] the smaller. Robust to either harness order.
    int n0 = in_sizes[0] / C_DIM;
    int n1 = in_sizes[1] / C_DIM;
    const float* X;
    const float* Cm;
    int N, K;
    if (n0 >= n1) {
        X  = (const float*)d_in[0]; N = n0;
        Cm = (const float*)d_in[1]; K = n1;
    } else {
        X  = (const float*)d_in[1]; N = n1;
        Cm = (const float*)d_in[0]; K = n0;
    }
    float* out = (float*)d_out;

    // Tripwire: 0xFF pattern is NaN as float32. If a failure reports
    // rel_err = NaN, the kernels never overwrote the buffer (launch problem);
    // if it reports a large finite value, values landed but dtype is wrong.
    cudaMemsetAsync(d_out, 0xFF, (size_t)out_size * sizeof(float), 0);

    // 1) centroid squared norms: one warp per centroid
    int c2_threads = 256;
    int c2_blocks  = (K * 32 + c2_threads - 1) / c2_threads;
    c2_kernel<<<c2_blocks, c2_threads>>>(Cm, K);

    // 2) fused GEMM + argmin: one block per 128 rows
    int blocks = (N + BM - 1) / BM;
    assign_kernel<<<blocks, 256>>>(X, Cm, out, K);
}

// round 8
// speedup vs baseline: 6.2391x; 6.2391x over previous
#include <cuda_runtime.h>
#include <cuda_bf16.h>

// ============================================================================
// KmeansAssigner: out[n] = argmin_k ( ||c_k||^2 - 2 * x_n . c_k )
// N=131072 C=512 K=2048.
//
// Round 8 (resubmit of R7 — infra failure, kernel never ran):
// bf16 mma.sync pipeline + cross-warp top-4 merge.
// R6 bug being fixed: 4 warps sharing the same rows (disjoint col slices)
// raced on out[row] with their subset argmins (rel_err 0.65 ~ 3/4 rows wrong).
// Fix: per-warp top-4 keys -> smem [row][wc][4], then one thread per row
// merges 16 keys into the global top-4, writes out, flags near-ties for
// exact fp32 refinement.
// ============================================================================

#define C_DIM 512
#define N_CAP 131072
#define K_CAP 2048
#define FLAG_CAP 65536
#define FLAG_THRESH 3.0f

#define SMEM_A_BYTES 131072            // 128 rows x 1024B
#define SMEM_B_BYTES 16384             // 128 cols x 128B
#define SMEM_TOTAL (SMEM_A_BYTES + 2 * SMEM_B_BYTES)

__device__ __nv_bfloat16 g_Xb[(size_t)N_CAP * C_DIM];
__device__ __nv_bfloat16 g_Cb[(size_t)K_CAP * C_DIM];
__device__ float g_c2[K_CAP];
__device__ int   g_flag_count;
__device__ int   g_flag_rows[FLAG_CAP];
__device__ int4  g_flag_cand[FLAG_CAP];

// ---------------------------------------------------------------------------
__device__ __forceinline__ unsigned smem_u32(const void* p) {
    unsigned a;
    asm("{ .reg .u64 t; cvta.to.shared.u64 t, %1; cvt.u32.u64 %0, t; }"
        : "=r"(a) : "l"(p));
    return a;
}
#define CP16(dst, src)                                                         \
    asm volatile("cp.async.cg.shared.global [%0], [%1], 16;"                   \
                 :: "r"(dst), "l"(src) : "memory")
#define CP_COMMIT() asm volatile("cp.async.commit_group;" ::: "memory")
#define CP_WAIT0()  asm volatile("cp.async.wait_group 0;" ::: "memory")
#define LDSM_X4(R, addr)                                                       \
    asm volatile("ldmatrix.sync.aligned.m8n8.x4.shared.b16 {%0,%1,%2,%3}, [%4];" \
                 : "=r"((R)[0]), "=r"((R)[1]), "=r"((R)[2]), "=r"((R)[3])      \
                 : "r"(addr))
#define MMA_BF16(Cc, A, B0, B1)                                                \
    asm volatile("mma.sync.aligned.m16n8k16.row.col.f32.bf16.bf16.f32 "        \
                 "{%0,%1,%2,%3}, {%4,%5,%6,%7}, {%8,%9}, {%0,%1,%2,%3};"       \
                 : "+f"((Cc)[0]), "+f"((Cc)[1]), "+f"((Cc)[2]), "+f"((Cc)[3])  \
                 : "r"((A)[0]), "r"((A)[1]), "r"((A)[2]), "r"((A)[3]),         \
                   "r"(B0), "r"(B1))

// A smem: row-major [128][512] bf16 (1024B rows), per-128B-block XOR swizzle.
__device__ __forceinline__ unsigned a_off(int row, int kb) {  // kb mult of 16
    return (unsigned)(row * 1024 + (kb & ~127) +
                      ((((kb >> 4) & 7) ^ (row & 7)) << 4));
}
// B smem: [128 cols][128B] (one 64-elem k-chunk per col), XOR swizzle.
__device__ __forceinline__ unsigned b_off(int col, int kb) {  // kb mult of 16
    return (unsigned)(col * 128 + ((((kb >> 4) & 7) ^ (col & 7)) << 4));
}

// order-preserving float->uint, low 11 bits replaced by col (tiebreak: low col)
__device__ __forceinline__ unsigned packkey(float s, int col) {
    unsigned u = __float_as_uint(s);
    u ^= (unsigned)(((int)u >> 31)) | 0x80000000u;
    return (u & ~2047u) | (unsigned)col;
}
__device__ __forceinline__ float unpackv(unsigned key) {
    unsigned u = (key & 0x80000000u) ? (key ^ 0x80000000u) : ~key;
    return __uint_as_float(u);
}
__device__ __forceinline__ void ins4(unsigned* t, unsigned k) {
    if (k < t[3]) {
        if (k < t[1]) {
            t[3] = t[2]; t[2] = t[1];
            if (k < t[0]) { t[1] = t[0]; t[0] = k; } else t[1] = k;
        } else {
            if (k < t[2]) { t[3] = t[2]; t[2] = k; } else t[3] = k;
        }
    }
}

// --- convert X to bf16 scratch; reset flag counter -------------------------
__global__ void convx_kernel(const float* __restrict__ X, int n4) {
    if (blockIdx.x == 0 && threadIdx.x == 0) g_flag_count = 0;
    int stride = (int)(gridDim.x * blockDim.x);
    for (int i = (int)(blockIdx.x * blockDim.x + threadIdx.x); i < n4;
         i += stride) {
        float4 v = ((const float4*)X)[i];
        __nv_bfloat16 b0 = __float2bfloat16(v.x), b1 = __float2bfloat16(v.y);
        __nv_bfloat16 b2 = __float2bfloat16(v.z), b3 = __float2bfloat16(v.w);
        ushort4 o;
        o.x = *(unsigned short*)&b0; o.y = *(unsigned short*)&b1;
        o.z = *(unsigned short*)&b2; o.w = *(unsigned short*)&b3;
        ((ushort4*)g_Xb)[i] = o;
    }
}

// --- centroid norms (fp32) + bf16 conversion, one warp per centroid --------
__global__ void c2_kernel(const float* __restrict__ cent, int K) {
    int warp = (int)((blockIdx.x * blockDim.x + threadIdx.x) >> 5);
    int lane = threadIdx.x & 31;
    if (warp >= K || warp >= K_CAP) return;
    const float* row = cent + (long long)warp * C_DIM;
    float s = 0.0f;
#pragma unroll
    for (int i = 0; i < C_DIM / 32; i++) {
        float v = row[lane + i * 32];
        g_Cb[(size_t)warp * C_DIM + lane + i * 32] = __float2bfloat16(v);
        s = fmaf(v, v, s);
    }
#pragma unroll
    for (int o = 16; o > 0; o >>= 1) s += __shfl_xor_sync(0xFFFFFFFFu, s, o);
    if (lane == 0) g_c2[warp] = s;
}

// --- B chunk staging (16KB: 128 cols x 64 k bf16) --------------------------
__device__ __forceinline__ void stage_B(unsigned sb, int T) {
    int nc = T >> 3, kk = T & 7, buf = T & 1;
    int tid = threadIdx.x;
    const __nv_bfloat16* srcb =
        g_Cb + ((size_t)nc * 128) * C_DIM + kk * 64;
    unsigned base = sb + SMEM_A_BYTES + (unsigned)buf * SMEM_B_BYTES;
#pragma unroll
    for (int i = 0; i < 4; i++) {
        int idx = tid + i * 256;
        int col = idx >> 3, u = idx & 7;
        unsigned dst = base + (unsigned)(col * 128 + ((u ^ (col & 7)) << 4));
        const void* s = srcb + (size_t)col * C_DIM + u * 8;
        CP16(dst, s);
    }
}

// --- main: bf16 mma.sync GEMM + fused top-4 argmin -------------------------
__global__ void __launch_bounds__(256, 1)
assign_mma(float* __restrict__ out, int K) {
    extern __shared__ char smem[];
    unsigned sb = smem_u32(smem);
    const int tid = threadIdx.x, lane = tid & 31, wid = tid >> 5;
    const int wr = wid >> 2, wc = wid & 3;   // warp grid 2 (rows) x 4 (cols)
    const int blockRow = (int)blockIdx.x * 128;

    // prologue: stage entire A tile (128 rows x 512 k bf16 = 128KB)
    {
        const __nv_bfloat16* src = g_Xb + (size_t)blockRow * C_DIM;
#pragma unroll
        for (int i = 0; i < 32; i++) {
            int idx = tid + i * 256;          // 16B unit 0..8191
            int row = idx >> 6, kbu = idx & 63;
            unsigned dst = sb + a_off(row, kbu * 16);
            const void* s = src + (size_t)row * C_DIM + kbu * 8;
            CP16(dst, s);
        }
    }
    stage_B(sb, 0);
    CP_COMMIT();
    CP_WAIT0();
    __syncthreads();

    float    acc[4][4][4];
    unsigned t4[8][4];
#pragma unroll
    for (int r = 0; r < 8; r++)
#pragma unroll
        for (int j = 0; j < 4; j++) t4[r][j] = 0xFFFFFFFFu;

    const int NT = (K / 128) * 8;
    for (int T = 0; T < NT; T++) {
        if ((T & 7) == 0) {
#pragma unroll
            for (int mt = 0; mt < 4; mt++)
#pragma unroll
                for (int nt = 0; nt < 4; nt++)
#pragma unroll
                    for (int j = 0; j < 4; j++) acc[mt][nt][j] = 0.0f;
        }
        if (T + 1 < NT) { stage_B(sb, T + 1); CP_COMMIT(); }

        unsigned bbase = sb + SMEM_A_BYTES + (unsigned)(T & 1) * SMEM_B_BYTES;
        int kchunk = (T & 7) * 128;          // byte offset within A row
#pragma unroll
        for (int ks = 0; ks < 4; ks++) {
            unsigned aa[4][4];
#pragma unroll
            for (int mt = 0; mt < 4; mt++) {
                int row = wr * 64 + mt * 16 + (lane & 15);
                int kb  = kchunk + ks * 32 + ((lane >> 4) << 4);
                unsigned addr = sb + a_off(row, kb);
                LDSM_X4(aa[mt], addr);
            }
            unsigned bb[2][4];
#pragma unroll
            for (int p = 0; p < 2; p++) {
                int col = wc * 32 + p * 16 + (lane & 7) + ((lane >> 4) & 1) * 8;
                int kbc = ks * 32 + (((lane >> 3) & 1) << 4);
                unsigned addr = bbase + b_off(col, kbc);
                LDSM_X4(bb[p], addr);
            }
#pragma unroll
            for (int mt = 0; mt < 4; mt++)
#pragma unroll
                for (int nt = 0; nt < 4; nt++)
                    MMA_BF16(acc[mt][nt], aa[mt],
                             bb[nt >> 1][(nt & 1) * 2],
                             bb[nt >> 1][(nt & 1) * 2 + 1]);
        }

        if ((T & 7) == 7) {                  // epilogue for col group nc
            int nc = T >> 3;
#pragma unroll
            for (int nt = 0; nt < 4; nt++)
#pragma unroll
                for (int c = 0; c < 2; c++) {
                    int col = nc * 128 + wc * 32 + nt * 8 + (lane & 3) * 2 + c;
                    float c2 = g_c2[col];
#pragma unroll
                    for (int mt = 0; mt < 4; mt++)
#pragma unroll
                        for (int h = 0; h < 2; h++) {
                            float s = fmaf(-2.0f, acc[mt][nt][h * 2 + c], c2);
                            ins4(t4[mt * 2 + h], packkey(s, col));
                        }
                }
        }
        CP_WAIT0();
        __syncthreads();
    }

    // merge top-4 across the 4 lanes of each quad (same rows, disjoint cols)
#pragma unroll
    for (int r = 0; r < 8; r++) {
#pragma unroll
        for (int x = 1; x <= 2; x <<= 1) {
            unsigned o0 = __shfl_xor_sync(0xFFFFFFFFu, t4[r][0], x);
            unsigned o1 = __shfl_xor_sync(0xFFFFFFFFu, t4[r][1], x);
            unsigned o2 = __shfl_xor_sync(0xFFFFFFFFu, t4[r][2], x);
            unsigned o3 = __shfl_xor_sync(0xFFFFFFFFu, t4[r][3], x);
            ins4(t4[r], o0); ins4(t4[r], o1); ins4(t4[r], o2); ins4(t4[r], o3);
        }
    }

    // === CROSS-WARP MERGE =====================================================
    // 4 warps (wc=0..3) hold disjoint col-subset top-4s for the same rows.
    // Stage per-warp keys to smem [row_local][wc][4] (reuses B region, dead
    // after the loop), then one thread per row merges all 16 keys.
    unsigned* keys = (unsigned*)(smem + SMEM_A_BYTES);   // 128*16*4B = 8KB
#pragma unroll
    for (int r = 0; r < 8; r++) {
        int mt = r >> 1, h = r & 1;
        if ((lane & 3) == mt) {
            int rl = wr * 64 + mt * 16 + (lane >> 2) + h * 8;
            uint4 v = make_uint4(t4[r][0], t4[r][1], t4[r][2], t4[r][3]);
            *(uint4*)&keys[rl * 16 + wc * 4] = v;
        }
    }
    __syncthreads();

    if (tid < 128) {
        unsigned g4[4] = {0xFFFFFFFFu, 0xFFFFFFFFu, 0xFFFFFFFFu, 0xFFFFFFFFu};
#pragma unroll
        for (int w = 0; w < 4; w++) {
            uint4 v = *(uint4*)&keys[tid * 16 + w * 4];
            ins4(g4, v.x); ins4(g4, v.y); ins4(g4, v.z); ins4(g4, v.w);
        }
        int row = blockRow + tid;
        out[row] = (float)(g4[0] & 2047u);
        float v1 = unpackv(g4[0]);
        float v2 = unpackv(g4[1]);
        if (v2 - v1 < FLAG_THRESH) {
            int ix = atomicAdd(&g_flag_count, 1);
            if (ix < FLAG_CAP) {
                g_flag_rows[ix] = row;
                g_flag_cand[ix] = make_int4(
                    (int)(g4[0] & 2047u), (int)(g4[1] & 2047u),
                    (int)(g4[2] & 2047u), (int)(g4[3] & 2047u));
            }
        }
    }
}

// --- exact fp32 refinement of flagged rows (warp per row, 4 candidates) ----
__global__ void refine_kernel(const float* __restrict__ X,
                              const float* __restrict__ Cm,
                              float* __restrict__ out) {
    int nf = g_flag_count; if (nf > FLAG_CAP) nf = FLAG_CAP;
    int gw = (int)((blockIdx.x * blockDim.x + threadIdx.x) >> 5);
    int lane = threadIdx.x & 31;
    int nwarps = (int)((gridDim.x * blockDim.x) >> 5);
    for (int i = gw; i < nf; i += nwarps) {
        int row = g_flag_rows[i];
        int4 cd = g_flag_cand[i];
        int cand[4] = {cd.x, cd.y, cd.z, cd.w};
        const float* x = X + (long long)row * C_DIM;
        float bv = 3.4e38f; int bi = 0x7FFFFFFF;
#pragma unroll
        for (int c = 0; c < 4; c++) {
            int col = cand[c];
            const float* ce = Cm + (long long)col * C_DIM;
            float p = 0.0f;
#pragma unroll
            for (int d = 0; d < C_DIM / 32; d++)
                p = fmaf(x[lane + d * 32], ce[lane + d * 32], p);
#pragma unroll
            for (int o = 16; o > 0; o >>= 1)
                p += __shfl_xor_sync(0xFFFFFFFFu, p, o);
            float s = fmaf(-2.0f, p, g_c2[col]);
            if (s < bv || (s == bv && col < bi)) { bv = s; bi = col; }
        }
        if (lane == 0) out[row] = (float)bi;
    }
}

// ============================================================================
extern "C" void kernel_launch(void* const* d_in, const int* in_sizes, int n_in,
                              void* d_out, int out_size) {
    int n0 = in_sizes[0] / C_DIM;
    int n1 = in_sizes[1] / C_DIM;
    const float* X; const float* Cm; int N, K;
    if (n0 >= n1) { X = (const float*)d_in[0]; N = n0;
                    Cm = (const float*)d_in[1]; K = n1; }
    else          { X = (const float*)d_in[1]; N = n1;
                    Cm = (const float*)d_in[0]; K = n0; }
    if (N > N_CAP) N = N_CAP;
    if (K > K_CAP) K = K_CAP;
    float* out = (float*)d_out;

    cudaFuncSetAttribute(assign_mma,
                         cudaFuncAttributeMaxDynamicSharedMemorySize,
                         SMEM_TOTAL);

    // 1) convert X to bf16 scratch (+ flag counter reset)
    convx_kernel<<<2048, 256>>>(X, N * C_DIM / 4);
    // 2) centroid norms + bf16 conversion
    c2_kernel<<<(K * 32 + 255) / 256, 256>>>(Cm, K);
    // 3) tensor-core GEMM + fused top-4 argmin
    assign_mma<<<N / 128, 256, SMEM_TOTAL>>>(out, K);
    // 4) exact fp32 refinement of near-tie rows
    refine_kernel<<<256, 256>>>(X, Cm, out);
}

// round 9
// speedup vs baseline: 6.6268x; 1.0621x over previous
#include <cuda_runtime.h>
#include <cuda_bf16.h>

// ============================================================================
// KmeansAssigner: out[n] = argmin_k ( ||c_k||^2 - 2 * x_n . c_k )
// N=131072 C=512 K=2048.
//
// Round 9: R8 (1235.6us) was 8 warps/SM (2/SMSP) -- too few to hide
// LDSM/MMA/cp.async latency (~45% of the legacy-HMMA path peak).
// Change: 512 threads/CTA, warp grid 4x4, warp tile 32x32. Same 128-row
// A tile, same smem (160KB), same B traffic; 16 warps/SM (4/SMSP).
// ============================================================================

#define C_DIM 512
#define N_CAP 131072
#define K_CAP 2048
#define FLAG_CAP 65536
#define FLAG_THRESH 3.0f

#define SMEM_A_BYTES 131072            // 128 rows x 1024B
#define SMEM_B_BYTES 16384             // 128 cols x 128B
#define SMEM_TOTAL (SMEM_A_BYTES + 2 * SMEM_B_BYTES)
#define NTHREADS 512

__device__ __nv_bfloat16 g_Xb[(size_t)N_CAP * C_DIM];
__device__ __nv_bfloat16 g_Cb[(size_t)K_CAP * C_DIM];
__device__ float g_c2[K_CAP];
__device__ int   g_flag_count;
__device__ int   g_flag_rows[FLAG_CAP];
__device__ int4  g_flag_cand[FLAG_CAP];

// ---------------------------------------------------------------------------
__device__ __forceinline__ unsigned smem_u32(const void* p) {
    unsigned a;
    asm("{ .reg .u64 t; cvta.to.shared.u64 t, %1; cvt.u32.u64 %0, t; }"
        : "=r"(a) : "l"(p));
    return a;
}
#define CP16(dst, src)                                                         \
    asm volatile("cp.async.cg.shared.global [%0], [%1], 16;"                   \
                 :: "r"(dst), "l"(src) : "memory")
#define CP_COMMIT() asm volatile("cp.async.commit_group;" ::: "memory")
#define CP_WAIT0()  asm volatile("cp.async.wait_group 0;" ::: "memory")
#define LDSM_X4(R, addr)                                                       \
    asm volatile("ldmatrix.sync.aligned.m8n8.x4.shared.b16 {%0,%1,%2,%3}, [%4];" \
                 : "=r"((R)[0]), "=r"((R)[1]), "=r"((R)[2]), "=r"((R)[3])      \
                 : "r"(addr))
#define MMA_BF16(Cc, A, B0, B1)                                                \
    asm volatile("mma.sync.aligned.m16n8k16.row.col.f32.bf16.bf16.f32 "        \
                 "{%0,%1,%2,%3}, {%4,%5,%6,%7}, {%8,%9}, {%0,%1,%2,%3};"       \
                 : "+f"((Cc)[0]), "+f"((Cc)[1]), "+f"((Cc)[2]), "+f"((Cc)[3])  \
                 : "r"((A)[0]), "r"((A)[1]), "r"((A)[2]), "r"((A)[3]),         \
                   "r"(B0), "r"(B1))

// A smem: row-major [128][512] bf16 (1024B rows), per-128B-block XOR swizzle.
__device__ __forceinline__ unsigned a_off(int row, int kb) {  // kb mult of 16
    return (unsigned)(row * 1024 + (kb & ~127) +
                      ((((kb >> 4) & 7) ^ (row & 7)) << 4));
}
// B smem: [128 cols][128B] (one 64-elem k-chunk per col), XOR swizzle.
__device__ __forceinline__ unsigned b_off(int col, int kb) {  // kb mult of 16
    return (unsigned)(col * 128 + ((((kb >> 4) & 7) ^ (col & 7)) << 4));
}

// order-preserving float->uint, low 11 bits replaced by col (tiebreak: low col)
__device__ __forceinline__ unsigned packkey(float s, int col) {
    unsigned u = __float_as_uint(s);
    u ^= (unsigned)(((int)u >> 31)) | 0x80000000u;
    return (u & ~2047u) | (unsigned)col;
}
__device__ __forceinline__ float unpackv(unsigned key) {
    unsigned u = (key & 0x80000000u) ? (key ^ 0x80000000u) : ~key;
    return __uint_as_float(u);
}
__device__ __forceinline__ void ins4(unsigned* t, unsigned k) {
    if (k < t[3]) {
        if (k < t[1]) {
            t[3] = t[2]; t[2] = t[1];
            if (k < t[0]) { t[1] = t[0]; t[0] = k; } else t[1] = k;
        } else {
            if (k < t[2]) { t[3] = t[2]; t[2] = k; } else t[3] = k;
        }
    }
}

// --- convert X to bf16 scratch; reset flag counter -------------------------
__global__ void convx_kernel(const float* __restrict__ X, int n4) {
    if (blockIdx.x == 0 && threadIdx.x == 0) g_flag_count = 0;
    int stride = (int)(gridDim.x * blockDim.x);
    for (int i = (int)(blockIdx.x * blockDim.x + threadIdx.x); i < n4;
         i += stride) {
        float4 v = ((const float4*)X)[i];
        __nv_bfloat16 b0 = __float2bfloat16(v.x), b1 = __float2bfloat16(v.y);
        __nv_bfloat16 b2 = __float2bfloat16(v.z), b3 = __float2bfloat16(v.w);
        ushort4 o;
        o.x = *(unsigned short*)&b0; o.y = *(unsigned short*)&b1;
        o.z = *(unsigned short*)&b2; o.w = *(unsigned short*)&b3;
        ((ushort4*)g_Xb)[i] = o;
    }
}

// --- centroid norms (fp32) + bf16 conversion, one warp per centroid --------
__global__ void c2_kernel(const float* __restrict__ cent, int K) {
    int warp = (int)((blockIdx.x * blockDim.x + threadIdx.x) >> 5);
    int lane = threadIdx.x & 31;
    if (warp >= K || warp >= K_CAP) return;
    const float* row = cent + (long long)warp * C_DIM;
    float s = 0.0f;
#pragma unroll
    for (int i = 0; i < C_DIM / 32; i++) {
        float v = row[lane + i * 32];
        g_Cb[(size_t)warp * C_DIM + lane + i * 32] = __float2bfloat16(v);
        s = fmaf(v, v, s);
    }
#pragma unroll
    for (int o = 16; o > 0; o >>= 1) s += __shfl_xor_sync(0xFFFFFFFFu, s, o);
    if (lane == 0) g_c2[warp] = s;
}

// --- B chunk staging (16KB: 128 cols x 64 k bf16) --------------------------
__device__ __forceinline__ void stage_B(unsigned sb, int T) {
    int nc = T >> 3, kk = T & 7, buf = T & 1;
    int tid = threadIdx.x;
    const __nv_bfloat16* srcb =
        g_Cb + ((size_t)nc * 128) * C_DIM + kk * 64;
    unsigned base = sb + SMEM_A_BYTES + (unsigned)buf * SMEM_B_BYTES;
#pragma unroll
    for (int i = 0; i < 2; i++) {
        int idx = tid + i * NTHREADS;
        int col = idx >> 3, u = idx & 7;
        unsigned dst = base + (unsigned)(col * 128 + ((u ^ (col & 7)) << 4));
        const void* s = srcb + (size_t)col * C_DIM + u * 8;
        CP16(dst, s);
    }
}

// --- main: bf16 mma.sync GEMM + fused top-4 argmin -------------------------
__global__ void __launch_bounds__(NTHREADS, 1)
assign_mma(float* __restrict__ out, int K) {
    extern __shared__ char smem[];
    unsigned sb = smem_u32(smem);
    const int tid = threadIdx.x, lane = tid & 31, wid = tid >> 5;
    const int wr = wid >> 2, wc = wid & 3;   // warp grid 4 (rows) x 4 (cols)
    const int blockRow = (int)blockIdx.x * 128;

    // prologue: stage entire A tile (128 rows x 512 k bf16 = 128KB)
    {
        const __nv_bfloat16* src = g_Xb + (size_t)blockRow * C_DIM;
#pragma unroll
        for (int i = 0; i < 16; i++) {
            int idx = tid + i * NTHREADS;     // 16B unit 0..8191
            int row = idx >> 6, kbu = idx & 63;
            unsigned dst = sb + a_off(row, kbu * 16);
            const void* s = src + (size_t)row * C_DIM + kbu * 8;
            CP16(dst, s);
        }
    }
    stage_B(sb, 0);
    CP_COMMIT();
    CP_WAIT0();
    __syncthreads();

    float    acc[2][4][4];                   // warp tile 32 rows x 32 cols
    unsigned t4[4][4];
#pragma unroll
    for (int r = 0; r < 4; r++)
#pragma unroll
        for (int j = 0; j < 4; j++) t4[r][j] = 0xFFFFFFFFu;

    const int NT = (K / 128) * 8;
    for (int T = 0; T < NT; T++) {
        if ((T & 7) == 0) {
#pragma unroll
            for (int mt = 0; mt < 2; mt++)
#pragma unroll
                for (int nt = 0; nt < 4; nt++)
#pragma unroll
                    for (int j = 0; j < 4; j++) acc[mt][nt][j] = 0.0f;
        }
        if (T + 1 < NT) { stage_B(sb, T + 1); CP_COMMIT(); }

        unsigned bbase = sb + SMEM_A_BYTES + (unsigned)(T & 1) * SMEM_B_BYTES;
        int kchunk = (T & 7) * 128;          // byte offset within A row
#pragma unroll
        for (int ks = 0; ks < 4; ks++) {
            unsigned aa[2][4];
#pragma unroll
            for (int mt = 0; mt < 2; mt++) {
                int row = wr * 32 + mt * 16 + (lane & 15);
                int kb  = kchunk + ks * 32 + ((lane >> 4) << 4);
                unsigned addr = sb + a_off(row, kb);
                LDSM_X4(aa[mt], addr);
            }
            unsigned bb[2][4];
#pragma unroll
            for (int p = 0; p < 2; p++) {
                int col = wc * 32 + p * 16 + (lane & 7) + ((lane >> 4) & 1) * 8;
                int kbc = ks * 32 + (((lane >> 3) & 1) << 4);
                unsigned addr = bbase + b_off(col, kbc);
                LDSM_X4(bb[p], addr);
            }
#pragma unroll
            for (int mt = 0; mt < 2; mt++)
#pragma unroll
                for (int nt = 0; nt < 4; nt++)
                    MMA_BF16(acc[mt][nt], aa[mt],
                             bb[nt >> 1][(nt & 1) * 2],
                             bb[nt >> 1][(nt & 1) * 2 + 1]);
        }

        if ((T & 7) == 7) {                  // epilogue for col group nc
            int nc = T >> 3;
#pragma unroll
            for (int nt = 0; nt < 4; nt++)
#pragma unroll
                for (int c = 0; c < 2; c++) {
                    int col = nc * 128 + wc * 32 + nt * 8 + (lane & 3) * 2 + c;
                    float c2 = g_c2[col];
#pragma unroll
                    for (int mt = 0; mt < 2; mt++)
#pragma unroll
                        for (int h = 0; h < 2; h++) {
                            float s = fmaf(-2.0f, acc[mt][nt][h * 2 + c], c2);
                            ins4(t4[mt * 2 + h], packkey(s, col));
                        }
                }
        }
        CP_WAIT0();
        __syncthreads();
    }

    // merge top-4 across the 4 lanes of each quad (same rows, disjoint cols)
#pragma unroll
    for (int r = 0; r < 4; r++) {
#pragma unroll
        for (int x = 1; x <= 2; x <<= 1) {
            unsigned o0 = __shfl_xor_sync(0xFFFFFFFFu, t4[r][0], x);
            unsigned o1 = __shfl_xor_sync(0xFFFFFFFFu, t4[r][1], x);
            unsigned o2 = __shfl_xor_sync(0xFFFFFFFFu, t4[r][2], x);
            unsigned o3 = __shfl_xor_sync(0xFFFFFFFFu, t4[r][3], x);
            ins4(t4[r], o0); ins4(t4[r], o1); ins4(t4[r], o2); ins4(t4[r], o3);
        }
    }

    // === CROSS-WARP MERGE ====================================================
    // 4 warps (wc=0..3) hold disjoint col-subset top-4s for the same rows.
    // Stage per-warp keys to smem [row_local][wc][4] (reuses B region, dead
    // after the loop), then one thread per row merges all 16 keys.
    unsigned* keys = (unsigned*)(smem + SMEM_A_BYTES);   // 128*16*4B = 8KB
#pragma unroll
    for (int r = 0; r < 4; r++) {
        int mt = r >> 1, h = r & 1;
        if ((lane & 3) == mt) {
            int rl = wr * 32 + mt * 16 + (lane >> 2) + h * 8;
            uint4 v = make_uint4(t4[r][0], t4[r][1], t4[r][2], t4[r][3]);
            *(uint4*)&keys[rl * 16 + wc * 4] = v;
        }
    }
    __syncthreads();

    if (tid < 128) {
        unsigned g4[4] = {0xFFFFFFFFu, 0xFFFFFFFFu, 0xFFFFFFFFu, 0xFFFFFFFFu};
#pragma unroll
        for (int w = 0; w < 4; w++) {
            uint4 v = *(uint4*)&keys[tid * 16 + w * 4];
            ins4(g4, v.x); ins4(g4, v.y); ins4(g4, v.z); ins4(g4, v.w);
        }
        int row = blockRow + tid;
        out[row] = (float)(g4[0] & 2047u);
        float v1 = unpackv(g4[0]);
        float v2 = unpackv(g4[1]);
        if (v2 - v1 < FLAG_THRESH) {
            int ix = atomicAdd(&g_flag_count, 1);
            if (ix < FLAG_CAP) {
                g_flag_rows[ix] = row;
                g_flag_cand[ix] = make_int4(
                    (int)(g4[0] & 2047u), (int)(g4[1] & 2047u),
                    (int)(g4[2] & 2047u), (int)(g4[3] & 2047u));
            }
        }
    }
}

// --- exact fp32 refinement of flagged rows (warp per row, 4 candidates) ----
__global__ void refine_kernel(const float* __restrict__ X,
                              const float* __restrict__ Cm,
                              float* __restrict__ out) {
    int nf = g_flag_count; if (nf > FLAG_CAP) nf = FLAG_CAP;
    int gw = (int)((blockIdx.x * blockDim.x + threadIdx.x) >> 5);
    int lane = threadIdx.x & 31;
    int nwarps = (int)((gridDim.x * blockDim.x) >> 5);
    for (int i = gw; i < nf; i += nwarps) {
        int row = g_flag_rows[i];
        int4 cd = g_flag_cand[i];
        int cand[4] = {cd.x, cd.y, cd.z, cd.w};
        const float* x = X + (long long)row * C_DIM;
        float bv = 3.4e38f; int bi = 0x7FFFFFFF;
#pragma unroll
        for (int c = 0; c < 4; c++) {
            int col = cand[c];
            const float* ce = Cm + (long long)col * C_DIM;
            float p = 0.0f;
#pragma unroll
            for (int d = 0; d < C_DIM / 32; d++)
                p = fmaf(x[lane + d * 32], ce[lane + d * 32], p);
#pragma unroll
            for (int o = 16; o > 0; o >>= 1)
                p += __shfl_xor_sync(0xFFFFFFFFu, p, o);
            float s = fmaf(-2.0f, p, g_c2[col]);
            if (s < bv || (s == bv && col < bi)) { bv = s; bi = col; }
        }
        if (lane == 0) out[row] = (float)bi;
    }
}

// ============================================================================
extern "C" void kernel_launch(void* const* d_in, const int* in_sizes, int n_in,
                              void* d_out, int out_size) {
    int n0 = in_sizes[0] / C_DIM;
    int n1 = in_sizes[1] / C_DIM;
    const float* X; const float* Cm; int N, K;
    if (n0 >= n1) { X = (const float*)d_in[0]; N = n0;
                    Cm = (const float*)d_in[1]; K = n1; }
    else          { X = (const float*)d_in[1]; N = n1;
                    Cm = (const float*)d_in[0]; K = n0; }
    if (N > N_CAP) N = N_CAP;
    if (K > K_CAP) K = K_CAP;
    float* out = (float*)d_out;

    cudaFuncSetAttribute(assign_mma,
                         cudaFuncAttributeMaxDynamicSharedMemorySize,
                         SMEM_TOTAL);

    // 1) convert X to bf16 scratch (+ flag counter reset)
    convx_kernel<<<2048, 256>>>(X, N * C_DIM / 4);
    // 2) centroid norms + bf16 conversion
    c2_kernel<<<(K * 32 + 255) / 256, 256>>>(Cm, K);
    // 3) tensor-core GEMM + fused top-4 argmin (512 threads, 16 warps)
    assign_mma<<<N / 128, NTHREADS, SMEM_TOTAL>>>(out, K);
    // 4) exact fp32 refinement of near-tie rows
    refine_kernel<<<256, 256>>>(X, Cm, out);
}

// round 10
// speedup vs baseline: 6.6308x; 1.0006x over previous
#include <cuda_runtime.h>
#include <cuda_bf16.h>

// ============================================================================
// KmeansAssigner: out[n] = argmin_k ( ||c_k||^2 - 2 * x_n . c_k )
// N=131072 C=512 K=2048.
//
// Round 9: R8 (1235.6us) was 8 warps/SM (2/SMSP) -- too few to hide
// LDSM/MMA/cp.async latency (~45% of the legacy-HMMA path peak).
// Change: 512 threads/CTA, warp grid 4x4, warp tile 32x32. Same 128-row
// A tile, same smem (160KB), same B traffic; 16 warps/SM (4/SMSP).
// ============================================================================

#define C_DIM 512
#define N_CAP 131072
#define K_CAP 2048
#define FLAG_CAP 65536
#define FLAG_THRESH 3.0f

#define SMEM_A_BYTES 131072            // 128 rows x 1024B
#define SMEM_B_BYTES 16384             // 128 cols x 128B
#define SMEM_TOTAL (SMEM_A_BYTES + 2 * SMEM_B_BYTES)
#define NTHREADS 512

__device__ __nv_bfloat16 g_Xb[(size_t)N_CAP * C_DIM];
__device__ __nv_bfloat16 g_Cb[(size_t)K_CAP * C_DIM];
__device__ float g_c2[K_CAP];
__device__ int   g_flag_count;
__device__ int   g_flag_rows[FLAG_CAP];
__device__ int4  g_flag_cand[FLAG_CAP];

// ---------------------------------------------------------------------------
__device__ __forceinline__ unsigned smem_u32(const void* p) {
    unsigned a;
    asm("{ .reg .u64 t; cvta.to.shared.u64 t, %1; cvt.u32.u64 %0, t; }"
        : "=r"(a) : "l"(p));
    return a;
}
#define CP16(dst, src)                                                         \
    asm volatile("cp.async.cg.shared.global [%0], [%1], 16;"                   \
                 :: "r"(dst), "l"(src) : "memory")
#define CP_COMMIT() asm volatile("cp.async.commit_group;" ::: "memory")
#define CP_WAIT0()  asm volatile("cp.async.wait_group 0;" ::: "memory")
#define LDSM_X4(R, addr)                                                       \
    asm volatile("ldmatrix.sync.aligned.m8n8.x4.shared.b16 {%0,%1,%2,%3}, [%4];" \
                 : "=r"((R)[0]), "=r"((R)[1]), "=r"((R)[2]), "=r"((R)[3])      \
                 : "r"(addr))
#define MMA_BF16(Cc, A, B0, B1)                                                \
    asm volatile("mma.sync.aligned.m16n8k16.row.col.f32.bf16.bf16.f32 "        \
                 "{%0,%1,%2,%3}, {%4,%5,%6,%7}, {%8,%9}, {%0,%1,%2,%3};"       \
                 : "+f"((Cc)[0]), "+f"((Cc)[1]), "+f"((Cc)[2]), "+f"((Cc)[3])  \
                 : "r"((A)[0]), "r"((A)[1]), "r"((A)[2]), "r"((A)[3]),         \
                   "r"(B0), "r"(B1))

// A smem: row-major [128][512] bf16 (1024B rows), per-128B-block XOR swizzle.
__device__ __forceinline__ unsigned a_off(int row, int kb) {  // kb mult of 16
    return (unsigned)(row * 1024 + (kb & ~127) +
                      ((((kb >> 4) & 7) ^ (row & 7)) << 4));
}
// B smem: [128 cols][128B] (one 64-elem k-chunk per col), XOR swizzle.
__device__ __forceinline__ unsigned b_off(int col, int kb) {  // kb mult of 16
    return (unsigned)(col * 128 + ((((kb >> 4) & 7) ^ (col & 7)) << 4));
}

// order-preserving float->uint, low 11 bits replaced by col (tiebreak: low col)
__device__ __forceinline__ unsigned packkey(float s, int col) {
    unsigned u = __float_as_uint(s);
    u ^= (unsigned)(((int)u >> 31)) | 0x80000000u;
    return (u & ~2047u) | (unsigned)col;
}
__device__ __forceinline__ float unpackv(unsigned key) {
    unsigned u = (key & 0x80000000u) ? (key ^ 0x80000000u) : ~key;
    return __uint_as_float(u);
}
__device__ __forceinline__ void ins4(unsigned* t, unsigned k) {
    if (k < t[3]) {
        if (k < t[1]) {
            t[3] = t[2]; t[2] = t[1];
            if (k < t[0]) { t[1] = t[0]; t[0] = k; } else t[1] = k;
        } else {
            if (k < t[2]) { t[3] = t[2]; t[2] = k; } else t[3] = k;
        }
    }
}

// --- convert X to bf16 scratch; reset flag counter -------------------------
__global__ void convx_kernel(const float* __restrict__ X, int n4) {
    if (blockIdx.x == 0 && threadIdx.x == 0) g_flag_count = 0;
    int stride = (int)(gridDim.x * blockDim.x);
    for (int i = (int)(blockIdx.x * blockDim.x + threadIdx.x); i < n4;
         i += stride) {
        float4 v = ((const float4*)X)[i];
        __nv_bfloat16 b0 = __float2bfloat16(v.x), b1 = __float2bfloat16(v.y);
        __nv_bfloat16 b2 = __float2bfloat16(v.z), b3 = __float2bfloat16(v.w);
        ushort4 o;
        o.x = *(unsigned short*)&b0; o.y = *(unsigned short*)&b1;
        o.z = *(unsigned short*)&b2; o.w = *(unsigned short*)&b3;
        ((ushort4*)g_Xb)[i] = o;
    }
}

// --- centroid norms (fp32) + bf16 conversion, one warp per centroid --------
__global__ void c2_kernel(const float* __restrict__ cent, int K) {
    int warp = (int)((blockIdx.x * blockDim.x + threadIdx.x) >> 5);
    int lane = threadIdx.x & 31;
    if (warp >= K || warp >= K_CAP) return;
    const float* row = cent + (long long)warp * C_DIM;
    float s = 0.0f;
#pragma unroll
    for (int i = 0; i < C_DIM / 32; i++) {
        float v = row[lane + i * 32];
        g_Cb[(size_t)warp * C_DIM + lane + i * 32] = __float2bfloat16(v);
        s = fmaf(v, v, s);
    }
#pragma unroll
    for (int o = 16; o > 0; o >>= 1) s += __shfl_xor_sync(0xFFFFFFFFu, s, o);
    if (lane == 0) g_c2[warp] = s;
}

// --- B chunk staging (16KB: 128 cols x 64 k bf16) --------------------------
__device__ __forceinline__ void stage_B(unsigned sb, int T) {
    int nc = T >> 3, kk = T & 7, buf = T & 1;
    int tid = threadIdx.x;
    const __nv_bfloat16* srcb =
        g_Cb + ((size_t)nc * 128) * C_DIM + kk * 64;
    unsigned base = sb + SMEM_A_BYTES + (unsigned)buf * SMEM_B_BYTES;
#pragma unroll
    for (int i = 0; i < 2; i++) {
        int idx = tid + i * NTHREADS;
        int col = idx >> 3, u = idx & 7;
        unsigned dst = base + (unsigned)(col * 128 + ((u ^ (col & 7)) << 4));
        const void* s = srcb + (size_t)col * C_DIM + u * 8;
        CP16(dst, s);
    }
}

// --- main: bf16 mma.sync GEMM + fused top-4 argmin -------------------------
__global__ void __launch_bounds__(NTHREADS, 1)
assign_mma(float* __restrict__ out, int K) {
    extern __shared__ char smem[];
    unsigned sb = smem_u32(smem);
    const int tid = threadIdx.x, lane = tid & 31, wid = tid >> 5;
    const int wr = wid >> 2, wc = wid & 3;   // warp grid 4 (rows) x 4 (cols)
    const int blockRow = (int)blockIdx.x * 128;

    // prologue: stage entire A tile (128 rows x 512 k bf16 = 128KB)
    {
        const __nv_bfloat16* src = g_Xb + (size_t)blockRow * C_DIM;
#pragma unroll
        for (int i = 0; i < 16; i++) {
            int idx = tid + i * NTHREADS;     // 16B unit 0..8191
            int row = idx >> 6, kbu = idx & 63;
            unsigned dst = sb + a_off(row, kbu * 16);
            const void* s = src + (size_t)row * C_DIM + kbu * 8;
            CP16(dst, s);
        }
    }
    stage_B(sb, 0);
    CP_COMMIT();
    CP_WAIT0();
    __syncthreads();

    float    acc[2][4][4];                   // warp tile 32 rows x 32 cols
    unsigned t4[4][4];
#pragma unroll
    for (int r = 0; r < 4; r++)
#pragma unroll
        for (int j = 0; j < 4; j++) t4[r][j] = 0xFFFFFFFFu;

    const int NT = (K / 128) * 8;
    for (int T = 0; T < NT; T++) {
        if ((T & 7) == 0) {
#pragma unroll
            for (int mt = 0; mt < 2; mt++)
#pragma unroll
                for (int nt = 0; nt < 4; nt++)
#pragma unroll
                    for (int j = 0; j < 4; j++) acc[mt][nt][j] = 0.0f;
        }
        if (T + 1 < NT) { stage_B(sb, T + 1); CP_COMMIT(); }

        unsigned bbase = sb + SMEM_A_BYTES + (unsigned)(T & 1) * SMEM_B_BYTES;
        int kchunk = (T & 7) * 128;          // byte offset within A row
#pragma unroll
        for (int ks = 0; ks < 4; ks++) {
            unsigned aa[2][4];
#pragma unroll
            for (int mt = 0; mt < 2; mt++) {
                int row = wr * 32 + mt * 16 + (lane & 15);
                int kb  = kchunk + ks * 32 + ((lane >> 4) << 4);
                unsigned addr = sb + a_off(row, kb);
                LDSM_X4(aa[mt], addr);
            }
            unsigned bb[2][4];
#pragma unroll
            for (int p = 0; p < 2; p++) {
                int col = wc * 32 + p * 16 + (lane & 7) + ((lane >> 4) & 1) * 8;
                int kbc = ks * 32 + (((lane >> 3) & 1) << 4);
                unsigned addr = bbase + b_off(col, kbc);
                LDSM_X4(bb[p], addr);
            }
#pragma unroll
            for (int mt = 0; mt < 2; mt++)
#pragma unroll
                for (int nt = 0; nt < 4; nt++)
                    MMA_BF16(acc[mt][nt], aa[mt],
                             bb[nt >> 1][(nt & 1) * 2],
                             bb[nt >> 1][(nt & 1) * 2 + 1]);
        }

        if ((T & 7) == 7) {                  // epilogue for col group nc
            int nc = T >> 3;
#pragma unroll
            for (int nt = 0; nt < 4; nt++)
#pragma unroll
                for (int c = 0; c < 2; c++) {
                    int col = nc * 128 + wc * 32 + nt * 8 + (lane & 3) * 2 + c;
                    float c2 = g_c2[col];
#pragma unroll
                    for (int mt = 0; mt < 2; mt++)
#pragma unroll
                        for (int h = 0; h < 2; h++) {
                            float s = fmaf(-2.0f, acc[mt][nt][h * 2 + c], c2);
                            ins4(t4[mt * 2 + h], packkey(s, col));
                        }
                }
        }
        CP_WAIT0();
        __syncthreads();
    }

    // merge top-4 across the 4 lanes of each quad (same rows, disjoint cols)
#pragma unroll
    for (int r = 0; r < 4; r++) {
#pragma unroll
        for (int x = 1; x <= 2; x <<= 1) {
            unsigned o0 = __shfl_xor_sync(0xFFFFFFFFu, t4[r][0], x);
            unsigned o1 = __shfl_xor_sync(0xFFFFFFFFu, t4[r][1], x);
            unsigned o2 = __shfl_xor_sync(0xFFFFFFFFu, t4[r][2], x);
            unsigned o3 = __shfl_xor_sync(0xFFFFFFFFu, t4[r][3], x);
            ins4(t4[r], o0); ins4(t4[r], o1); ins4(t4[r], o2); ins4(t4[r], o3);
        }
    }

    // === CROSS-WARP MERGE ====================================================
    // 4 warps (wc=0..3) hold disjoint col-subset top-4s for the same rows.
    // Stage per-warp keys to smem [row_local][wc][4] (reuses B region, dead
    // after the loop), then one thread per row merges all 16 keys.
    unsigned* keys = (unsigned*)(smem + SMEM_A_BYTES);   // 128*16*4B = 8KB
#pragma unroll
    for (int r = 0; r < 4; r++) {
        int mt = r >> 1, h = r & 1;
        if ((lane & 3) == mt) {
            int rl = wr * 32 + mt * 16 + (lane >> 2) + h * 8;
            uint4 v = make_uint4(t4[r][0], t4[r][1], t4[r][2], t4[r][3]);
            *(uint4*)&keys[rl * 16 + wc * 4] = v;
        }
    }
    __syncthreads();

    if (tid < 128) {
        unsigned g4[4] = {0xFFFFFFFFu, 0xFFFFFFFFu, 0xFFFFFFFFu, 0xFFFFFFFFu};
#pragma unroll
        for (int w = 0; w < 4; w++) {
            uint4 v = *(uint4*)&keys[tid * 16 + w * 4];
            ins4(g4, v.x); ins4(g4, v.y); ins4(g4, v.z); ins4(g4, v.w);
        }
        int row = blockRow + tid;
        out[row] = (float)(g4[0] & 2047u);
        float v1 = unpackv(g4[0]);
        float v2 = unpackv(g4[1]);
        if (v2 - v1 < FLAG_THRESH) {
            int ix = atomicAdd(&g_flag_count, 1);
            if (ix < FLAG_CAP) {
                g_flag_rows[ix] = row;
                g_flag_cand[ix] = make_int4(
                    (int)(g4[0] & 2047u), (int)(g4[1] & 2047u),
                    (int)(g4[2] & 2047u), (int)(g4[3] & 2047u));
            }
        }
    }
}

// --- exact fp32 refinement of flagged rows (warp per row, 4 candidates) ----
__global__ void refine_kernel(const float* __restrict__ X,
                              const float* __restrict__ Cm,
                              float* __restrict__ out) {
    int nf = g_flag_count; if (nf > FLAG_CAP) nf = FLAG_CAP;
    int gw = (int)((blockIdx.x * blockDim.x + threadIdx.x) >> 5);
    int lane = threadIdx.x & 31;
    int nwarps = (int)((gridDim.x * blockDim.x) >> 5);
    for (int i = gw; i < nf; i += nwarps) {
        int row = g_flag_rows[i];
        int4 cd = g_flag_cand[i];
        int cand[4] = {cd.x, cd.y, cd.z, cd.w};
        const float* x = X + (long long)row * C_DIM;
        float bv = 3.4e38f; int bi = 0x7FFFFFFF;
#pragma unroll
        for (int c = 0; c < 4; c++) {
            int col = cand[c];
            const float* ce = Cm + (long long)col * C_DIM;
            float p = 0.0f;
#pragma unroll
            for (int d = 0; d < C_DIM / 32; d++)
                p = fmaf(x[lane + d * 32], ce[lane + d * 32], p);
#pragma unroll
            for (int o = 16; o > 0; o >>= 1)
                p += __shfl_xor_sync(0xFFFFFFFFu, p, o);
            float s = fmaf(-2.0f, p, g_c2[col]);
            if (s < bv || (s == bv && col < bi)) { bv = s; bi = col; }
        }
        if (lane == 0) out[row] = (float)bi;
    }
}

// ============================================================================
extern "C" void kernel_launch(void* const* d_in, const int* in_sizes, int n_in,
                              void* d_out, int out_size) {
    int n0 = in_sizes[0] / C_DIM;
    int n1 = in_sizes[1] / C_DIM;
    const float* X; const float* Cm; int N, K;
    if (n0 >= n1) { X = (const float*)d_in[0]; N = n0;
                    Cm = (const float*)d_in[1]; K = n1; }
    else          { X = (const float*)d_in[1]; N = n1;
                    Cm = (const float*)d_in[0]; K = n0; }
    if (N > N_CAP) N = N_CAP;
    if (K > K_CAP) K = K_CAP;
    float* out = (float*)d_out;

    cudaFuncSetAttribute(assign_mma,
                         cudaFuncAttributeMaxDynamicSharedMemorySize,
                         SMEM_TOTAL);

    // 1) convert X to bf16 scratch (+ flag counter reset)
    convx_kernel<<<2048, 256>>>(X, N * C_DIM / 4);
    // 2) centroid norms + bf16 conversion
    c2_kernel<<<(K * 32 + 255) / 256, 256>>>(Cm, K);
    // 3) tensor-core GEMM + fused top-4 argmin (512 threads, 16 warps)
    assign_mma<<<N / 128, NTHREADS, SMEM_TOTAL>>>(out, K);
    // 4) exact fp32 refinement of near-tie rows
    refine_kernel<<<256, 256>>>(X, Cm, out);
}

// round 13
// speedup vs baseline: 10.0868x; 1.5212x over previous
#include <cuda_runtime.h>

// ============================================================================
// KmeansAssigner: out[n] = argmin_k ( ||c_k||^2 - 2 * x_n . c_k )
// N=131072 C=512 K=2048.
//
// Round 13 (resubmit of R12 — infra failure, kernel never ran):
// legacy bf16 mma.sync pipe measured at rt~16cyc (270 TF/s) and R9/R11 sat AT
// it. Switch the GEMM to INT8 mma.sync.m16n8k32.s8 (historically 2x the fp16
// FLOP rate on this pipe). Per-row symmetric quantization (scale=rowmax/127);
// epilogue rescales dot32 by sx[row]*sc[col]; top-4 candidates + exact fp32
// refine of rows with approx gap < 6.0 (~6 sigma of the int8 error diff).
// ============================================================================

#define C_DIM 512
#define N_CAP 131072
#define K_CAP 2048
#define FLAG_CAP 65536
#define FLAG_THRESH 6.0f

#define SMEM_A_BYTES 65536             // 128 rows x 512B (int8)
#define SMEM_B_BYTES 16384             // 128 cols x 128B (int8 k-chunk)
#define SMEM_SX_OFF  (SMEM_A_BYTES + 2 * SMEM_B_BYTES)
#define SMEM_TOTAL   (SMEM_SX_OFF + 512)
#define NTHREADS 512

__device__ signed char g_X8[(size_t)N_CAP * C_DIM];
__device__ signed char g_C8[(size_t)K_CAP * C_DIM];
__device__ float g_sx[N_CAP];
__device__ float g_sc[K_CAP];
__device__ float g_c2[K_CAP];
__device__ int   g_flag_count;
__device__ int   g_flag_rows[FLAG_CAP];
__device__ int4  g_flag_cand[FLAG_CAP];

// ---------------------------------------------------------------------------
__device__ __forceinline__ unsigned smem_u32(const void* p) {
    unsigned a;
    asm("{ .reg .u64 t; cvta.to.shared.u64 t, %1; cvt.u32.u64 %0, t; }"
        : "=r"(a) : "l"(p));
    return a;
}
#define CP16(dst, src)                                                         \
    asm volatile("cp.async.cg.shared.global [%0], [%1], 16;"                   \
                 :: "r"(dst), "l"(src) : "memory")
#define CP_COMMIT() asm volatile("cp.async.commit_group;" ::: "memory")
#define CP_WAIT0()  asm volatile("cp.async.wait_group 0;" ::: "memory")
#define LDSM_X4(R, addr)                                                       \
    asm volatile("ldmatrix.sync.aligned.m8n8.x4.shared.b16 {%0,%1,%2,%3}, [%4];" \
                 : "=r"((R)[0]), "=r"((R)[1]), "=r"((R)[2]), "=r"((R)[3])      \
                 : "r"(addr))
#define MMA_S8(Cc, A, B0, B1)                                                  \
    asm volatile("mma.sync.aligned.m16n8k32.row.col.s32.s8.s8.s32 "            \
                 "{%0,%1,%2,%3}, {%4,%5,%6,%7}, {%8,%9}, {%0,%1,%2,%3};"       \
                 : "+r"((Cc)[0]), "+r"((Cc)[1]), "+r"((Cc)[2]), "+r"((Cc)[3])  \
                 : "r"((A)[0]), "r"((A)[1]), "r"((A)[2]), "r"((A)[3]),         \
                   "r"(B0), "r"(B1))

// A smem: [128 rows][512B], XOR swizzle inside 128B blocks (kb mult of 16).
__device__ __forceinline__ unsigned a_off(int row, int kb) {
    return (unsigned)(row * 512 + (kb & ~127) +
                      ((((kb >> 4) & 7) ^ (row & 7)) << 4));
}
// B smem: [128 cols][128B] (one 128-elem int8 k-chunk per col), XOR swizzle.
__device__ __forceinline__ unsigned b_off(int col, int kb) {
    return (unsigned)(col * 128 + ((((kb >> 4) & 7) ^ (col & 7)) << 4));
}

// order-preserving float->uint, low 11 bits replaced by col (tiebreak low col)
__device__ __forceinline__ unsigned packkey(float s, int col) {
    unsigned u = __float_as_uint(s);
    u ^= (unsigned)(((int)u >> 31)) | 0x80000000u;
    return (u & ~2047u) | (unsigned)col;
}
__device__ __forceinline__ float unpackv(unsigned key) {
    unsigned u = (key & 0x80000000u) ? (key ^ 0x80000000u) : ~key;
    return __uint_as_float(u);
}
__device__ __forceinline__ void ins4(unsigned* t, unsigned k) {
    if (k < t[3]) {
        if (k < t[1]) {
            t[3] = t[2]; t[2] = t[1];
            if (k < t[0]) { t[1] = t[0]; t[0] = k; } else t[1] = k;
        } else {
            if (k < t[2]) { t[3] = t[2]; t[2] = k; } else t[3] = k;
        }
    }
}
__device__ __forceinline__ int q8(float v, float inv) {
    int q = __float2int_rn(v * inv);
    return q < -127 ? -127 : (q > 127 ? 127 : q);
}
__device__ __forceinline__ unsigned pack4(const float* v, float inv) {
    return (unsigned)(q8(v[0], inv) & 255) |
           ((unsigned)(q8(v[1], inv) & 255) << 8) |
           ((unsigned)(q8(v[2], inv) & 255) << 16) |
           ((unsigned)(q8(v[3], inv) & 255) << 24);
}

// --- quantize X rows to int8 (per-row scale); reset flag counter -----------
__global__ void convx8_kernel(const float* __restrict__ X, int N) {
    if (blockIdx.x == 0 && threadIdx.x == 0) g_flag_count = 0;
    int row = (int)blockIdx.x * 8 + (threadIdx.x >> 5);
    int lane = threadIdx.x & 31;
    if (row >= N) return;
    const float4* src = (const float4*)(X + (size_t)row * C_DIM) + lane * 4;
    float4 v[4];
    float mx = 0.0f;
#pragma unroll
    for (int i = 0; i < 4; i++) {
        v[i] = src[i];
        mx = fmaxf(mx, fmaxf(fmaxf(fabsf(v[i].x), fabsf(v[i].y)),
                             fmaxf(fabsf(v[i].z), fabsf(v[i].w))));
    }
#pragma unroll
    for (int o = 16; o > 0; o >>= 1)
        mx = fmaxf(mx, __shfl_xor_sync(0xFFFFFFFFu, mx, o));
    mx = fmaxf(mx, 1e-20f);
    float inv = 127.0f / mx;
    int4 p;
    p.x = (int)pack4(&v[0].x, inv);
    p.y = (int)pack4(&v[1].x, inv);
    p.z = (int)pack4(&v[2].x, inv);
    p.w = (int)pack4(&v[3].x, inv);
    ((int4*)(g_X8 + (size_t)row * C_DIM))[lane] = p;
    if (lane == 0) g_sx[row] = mx / 127.0f;
}

// --- centroid: exact ||c||^2 (fp32) + int8 quantization, warp per row ------
__global__ void c2s_kernel(const float* __restrict__ cent, int K) {
    int row = (int)((blockIdx.x * blockDim.x + threadIdx.x) >> 5);
    int lane = threadIdx.x & 31;
    if (row >= K || row >= K_CAP) return;
    const float4* src = (const float4*)(cent + (size_t)row * C_DIM) + lane * 4;
    float4 v[4];
    float mx = 0.0f, s2 = 0.0f;
#pragma unroll
    for (int i = 0; i < 4; i++) {
        v[i] = src[i];
        mx = fmaxf(mx, fmaxf(fmaxf(fabsf(v[i].x), fabsf(v[i].y)),
                             fmaxf(fabsf(v[i].z), fabsf(v[i].w))));
        s2 = fmaf(v[i].x, v[i].x, s2); s2 = fmaf(v[i].y, v[i].y, s2);
        s2 = fmaf(v[i].z, v[i].z, s2); s2 = fmaf(v[i].w, v[i].w, s2);
    }
#pragma unroll
    for (int o = 16; o > 0; o >>= 1) {
        mx = fmaxf(mx, __shfl_xor_sync(0xFFFFFFFFu, mx, o));
        s2 += __shfl_xor_sync(0xFFFFFFFFu, s2, o);
    }
    mx = fmaxf(mx, 1e-20f);
    float inv = 127.0f / mx;
    int4 p;
    p.x = (int)pack4(&v[0].x, inv);
    p.y = (int)pack4(&v[1].x, inv);
    p.z = (int)pack4(&v[2].x, inv);
    p.w = (int)pack4(&v[3].x, inv);
    ((int4*)(g_C8 + (size_t)row * C_DIM))[lane] = p;
    if (lane == 0) { g_sc[row] = mx / 127.0f; g_c2[row] = s2; }
}

// --- B chunk staging (16KB: 128 cols x 128 int8 k) -------------------------
__device__ __forceinline__ void stage_B(unsigned sb, int T) {
    int nc = T >> 2, kk = T & 3, buf = T & 1;
    int tid = threadIdx.x;
    const signed char* srcb = g_C8 + ((size_t)nc * 128) * C_DIM + kk * 128;
    unsigned base = sb + SMEM_A_BYTES + (unsigned)buf * SMEM_B_BYTES;
#pragma unroll
    for (int i = 0; i < 2; i++) {
        int idx = tid + i * NTHREADS;         // 16B granule 0..1023
        int col = idx >> 3, u = idx & 7;
        unsigned dst = base + (unsigned)(col * 128 + ((u ^ (col & 7)) << 4));
        const void* s = srcb + (size_t)col * C_DIM + u * 16;
        CP16(dst, s);
    }
}

// --- main: int8 mma.sync GEMM + fused top-4 argmin -------------------------
__global__ void __launch_bounds__(NTHREADS, 1)
assign_mma(float* __restrict__ out, int K) {
    extern __shared__ char smem[];
    unsigned sb = smem_u32(smem);
    const int tid = threadIdx.x, lane = tid & 31, wid = tid >> 5;
    const int wr = wid >> 2, wc = wid & 3;   // warp grid 4 (rows) x 4 (cols)
    const int blockRow = (int)blockIdx.x * 128;
    float* sxs = (float*)(smem + SMEM_SX_OFF);

    // prologue: stage A tile (128 rows x 512 int8 = 64KB) + sx + B chunk 0
    {
        const signed char* src = g_X8 + (size_t)blockRow * C_DIM;
#pragma unroll
        for (int i = 0; i < 8; i++) {
            int idx = tid + i * NTHREADS;     // 16B granule 0..4095
            int row = idx >> 5, u = idx & 31;
            unsigned dst = sb + a_off(row, u * 16);
            const void* s = src + (size_t)row * C_DIM + u * 16;
            CP16(dst, s);
        }
    }
    if (tid < 128) sxs[tid] = g_sx[blockRow + tid];
    stage_B(sb, 0);
    CP_COMMIT();
    CP_WAIT0();
    __syncthreads();

    // per-thread row scales (rows: wr*32 + mt*16 + h*8 + lane/4)
    float sxr[4];
#pragma unroll
    for (int r = 0; r < 4; r++)
        sxr[r] = sxs[wr * 32 + (r >> 1) * 16 + (r & 1) * 8 + (lane >> 2)];

    int      acc[2][4][4];                   // warp tile 32 rows x 32 cols
    unsigned t4[4][4];
#pragma unroll
    for (int r = 0; r < 4; r++)
#pragma unroll
        for (int j = 0; j < 4; j++) t4[r][j] = 0xFFFFFFFFu;

    const int NT = (K / 128) * 4;            // 4 chunks of k=128 per group
    for (int T = 0; T < NT; T++) {
        if ((T & 3) == 0) {
#pragma unroll
            for (int mt = 0; mt < 2; mt++)
#pragma unroll
                for (int nt = 0; nt < 4; nt++)
#pragma unroll
                    for (int j = 0; j < 4; j++) acc[mt][nt][j] = 0;
        }
        if (T + 1 < NT) { stage_B(sb, T + 1); CP_COMMIT(); }

        unsigned bbase = sb + SMEM_A_BYTES + (unsigned)(T & 1) * SMEM_B_BYTES;
        int kchunk = (T & 3) * 128;          // byte offset within A row
#pragma unroll
        for (int ks = 0; ks < 4; ks++) {     // 4 x k32 per chunk
            unsigned aa[2][4];
#pragma unroll
            for (int mt = 0; mt < 2; mt++) {
                // x4: (rows 0-7,kb)(rows 8-15,kb)(rows 0-7,kb+16)(rows 8-15,kb+16)
                int row = wr * 32 + mt * 16 + ((lane >> 3) & 1) * 8 + (lane & 7);
                int kb  = kchunk + ks * 32 + ((lane >> 4) << 4);
                LDSM_X4(aa[mt], sb + a_off(row, kb));
            }
            unsigned bb[2][4];
#pragma unroll
            for (int p = 0; p < 2; p++) {
                // x4: (cols 0-7,kb)(cols 0-7,kb+16)(cols 8-15,kb)(cols 8-15,kb+16)
                int col = wc * 32 + p * 16 + ((lane >> 4) & 1) * 8 + (lane & 7);
                int kb  = ks * 32 + (((lane >> 3) & 1) << 4);
                LDSM_X4(bb[p], bbase + b_off(col, kb));
            }
#pragma unroll
            for (int mt = 0; mt < 2; mt++)
#pragma unroll
                for (int nt = 0; nt < 4; nt++)
                    MMA_S8(acc[mt][nt], aa[mt],
                           bb[nt >> 1][(nt & 1) * 2],
                           bb[nt >> 1][(nt & 1) * 2 + 1]);
        }

        if ((T & 3) == 3) {                  // epilogue for col group nc
            int nc = T >> 2;
#pragma unroll
            for (int nt = 0; nt < 4; nt++)
#pragma unroll
                for (int c = 0; c < 2; c++) {
                    int col = nc * 128 + wc * 32 + nt * 8 + (lane & 3) * 2 + c;
                    float c2v = g_c2[col];
                    float scv = g_sc[col];
#pragma unroll
                    for (int mt = 0; mt < 2; mt++)
#pragma unroll
                        for (int h = 0; h < 2; h++) {
                            float dotf = (float)acc[mt][nt][h * 2 + c];
                            float s = fmaf(-2.0f * sxr[mt * 2 + h] * scv,
                                           dotf, c2v);
                            ins4(t4[mt * 2 + h], packkey(s, col));
                        }
                }
        }
        CP_WAIT0();
        __syncthreads();
    }

    // merge top-4 across the 4 lanes of each quad (same rows, disjoint cols)
#pragma unroll
    for (int r = 0; r < 4; r++) {
#pragma unroll
        for (int x = 1; x <= 2; x <<= 1) {
            unsigned o0 = __shfl_xor_sync(0xFFFFFFFFu, t4[r][0], x);
            unsigned o1 = __shfl_xor_sync(0xFFFFFFFFu, t4[r][1], x);
            unsigned o2 = __shfl_xor_sync(0xFFFFFFFFu, t4[r][2], x);
            unsigned o3 = __shfl_xor_sync(0xFFFFFFFFu, t4[r][3], x);
            ins4(t4[r], o0); ins4(t4[r], o1); ins4(t4[r], o2); ins4(t4[r], o3);
        }
    }

    // cross-warp merge: per-warp keys -> smem [row][wc][4] (reuses B region)
    unsigned* keys = (unsigned*)(smem + SMEM_A_BYTES);   // 128*16*4B = 8KB
#pragma unroll
    for (int r = 0; r < 4; r++) {
        int mt = r >> 1, h = r & 1;
        if ((lane & 3) == mt) {
            int rl = wr * 32 + mt * 16 + (lane >> 2) + h * 8;
            uint4 v = make_uint4(t4[r][0], t4[r][1], t4[r][2], t4[r][3]);
            *(uint4*)&keys[rl * 16 + wc * 4] = v;
        }
    }
    __syncthreads();

    if (tid < 128) {
        unsigned g4[4] = {0xFFFFFFFFu, 0xFFFFFFFFu, 0xFFFFFFFFu, 0xFFFFFFFFu};
#pragma unroll
        for (int w = 0; w < 4; w++) {
            uint4 v = *(uint4*)&keys[tid * 16 + w * 4];
            ins4(g4, v.x); ins4(g4, v.y); ins4(g4, v.z); ins4(g4, v.w);
        }
        int row = blockRow + tid;
        out[row] = (float)(g4[0] & 2047u);
        float v1 = unpackv(g4[0]);
        float v2 = unpackv(g4[1]);
        if (v2 - v1 < FLAG_THRESH) {
            int ix = atomicAdd(&g_flag_count, 1);
            if (ix < FLAG_CAP) {
                g_flag_rows[ix] = row;
                g_flag_cand[ix] = make_int4(
                    (int)(g4[0] & 2047u), (int)(g4[1] & 2047u),
                    (int)(g4[2] & 2047u), (int)(g4[3] & 2047u));
            }
        }
    }
}

// --- exact fp32 refinement of flagged rows (warp per row, 4 candidates) ----
__global__ void refine_kernel(const float* __restrict__ X,
                              const float* __restrict__ Cm,
                              float* __restrict__ out) {
    int nf = g_flag_count; if (nf > FLAG_CAP) nf = FLAG_CAP;
    int gw = (int)((blockIdx.x * blockDim.x + threadIdx.x) >> 5);
    int lane = threadIdx.x & 31;
    int nwarps = (int)((gridDim.x * blockDim.x) >> 5);
    for (int i = gw; i < nf; i += nwarps) {
        int row = g_flag_rows[i];
        int4 cd = g_flag_cand[i];
        int cand[4] = {cd.x, cd.y, cd.z, cd.w};
        const float* x = X + (long long)row * C_DIM;
        float bv = 3.4e38f; int bi = 0x7FFFFFFF;
#pragma unroll
        for (int c = 0; c < 4; c++) {
            int col = cand[c];
            const float* ce = Cm + (long long)col * C_DIM;
            float p = 0.0f;
#pragma unroll
            for (int d = 0; d < C_DIM / 32; d++)
                p = fmaf(x[lane + d * 32], ce[lane + d * 32], p);
#pragma unroll
            for (int o = 16; o > 0; o >>= 1)
                p += __shfl_xor_sync(0xFFFFFFFFu, p, o);
            float s = fmaf(-2.0f, p, g_c2[col]);
            if (s < bv || (s == bv && col < bi)) { bv = s; bi = col; }
        }
        if (lane == 0) out[row] = (float)bi;
    }
}

// ============================================================================
extern "C" void kernel_launch(void* const* d_in, const int* in_sizes, int n_in,
                              void* d_out, int out_size) {
    int n0 = in_sizes[0] / C_DIM;
    int n1 = in_sizes[1] / C_DIM;
    const float* X; const float* Cm; int N, K;
    if (n0 >= n1) { X = (const float*)d_in[0]; N = n0;
                    Cm = (const float*)d_in[1]; K = n1; }
    else          { X = (const float*)d_in[1]; N = n1;
                    Cm = (const float*)d_in[0]; K = n0; }
    if (N > N_CAP) N = N_CAP;
    if (K > K_CAP) K = K_CAP;
    float* out = (float*)d_out;

    cudaFuncSetAttribute(assign_mma,
                         cudaFuncAttributeMaxDynamicSharedMemorySize,
                         SMEM_TOTAL);

    // 1) quantize X to int8 (per-row scale) + flag counter reset
    convx8_kernel<<<(N + 7) / 8, 256>>>(X, N);
    // 2) centroid exact norms + int8 quantization
    c2s_kernel<<<(K * 32 + 255) / 256, 256>>>(Cm, K);
    // 3) int8 tensor-core GEMM + fused top-4 argmin
    assign_mma<<<N / 128, NTHREADS, SMEM_TOTAL>>>(out, K);
    // 4) exact fp32 refinement of near-tie rows
    refine_kernel<<<256, 256>>>(X, Cm, out);
}